// round 14
// baseline (speedup 1.0000x reference)
#include <cuda_runtime.h>
#include <cstdint>

#define N_NODES 100000
#define N_EDGES 1000000
#define D 64
#define LATENT 32
#define OUT_DIM 64
#define CAP 64
#define NB_BUCKET 3907             // ceil(1e6 / 256)
#define NB_NODE 1563               // ceil(100k / 64)
#define GATHER_BLOCKS 444          // 148 SMs x 3 blocks
#define XS2_STRIDE 66              // float2 units; 528B rows -> 16B aligned

// Scratch (BSS-zeroed at load; fully overwritten / self-resetting each call)
__device__ int   g_cnti[N_NODES];
__device__ int   g_bucket[(size_t)N_NODES * CAP];   // 25.6 MB edge ids
__device__ float g_sums[(size_t)N_NODES * D];       // mean(edge) per node
__device__ float g_hpre[(size_t)N_NODES * LATENT];  // node_attr @ W1[0:64]
__device__ float g_G[64 * LATENT];                  // global @ W1[128:192] + b1
__device__ float g_zero[D];                         // never written: stays 0

// ---------------------------------------------------------------------------
// f32x2 packed helpers (Blackwell FFMA2/FADD2 — only reachable via PTX)
// ---------------------------------------------------------------------------
__device__ __forceinline__ uint64_t pack2(float a, float b) {
    uint64_t r; asm("mov.b64 %0, {%1, %2};" : "=l"(r) : "f"(a), "f"(b)); return r;
}
__device__ __forceinline__ void unpack2(uint64_t v, float& a, float& b) {
    asm("mov.b64 {%0, %1}, %2;" : "=f"(a), "=f"(b) : "l"(v));
}
__device__ __forceinline__ void ffma2(uint64_t& acc, uint64_t x, uint64_t w) {
    asm("fma.rn.f32x2 %0, %1, %2, %0;" : "+l"(acc) : "l"(x), "l"(w));
}
__device__ __forceinline__ void fadd2(uint64_t& acc, uint64_t x) {
    asm("add.rn.f32x2 %0, %0, %1;" : "+l"(acc) : "l"(x));
}

// ---------------------------------------------------------------------------
// Kernel K1: [bucket build | node-proj | G]
// ---------------------------------------------------------------------------
__global__ __launch_bounds__(256)
void prep_kernel(const int* __restrict__ recv,
                 const float* __restrict__ node_attr,
                 const float* __restrict__ global_attr,
                 const float* __restrict__ W1,
                 const float* __restrict__ b1) {
    __shared__ float sW[2048];   // 8 KB weight tile
    __shared__ float sb[LATENT];
    const int tid = threadIdx.x;

    if (blockIdx.x < NB_BUCKET) {
        int e = blockIdx.x * 256 + tid;
        if (e < N_EDGES) {
            int r = __ldg(&recv[e]);
            int pos = atomicAdd(&g_cnti[r], 1);
            if (pos < CAP) g_bucket[(size_t)r * CAP + pos] = e;
        }
        return;
    }

    if (blockIdx.x < NB_BUCKET + NB_NODE) {
        // node projection: hpre[n][j] = node[n][0:64] . W1[0:64][j]
        const int tile = (blockIdx.x - NB_BUCKET) * 64;
        const int lane = tid & 31, p = tid >> 5;
        for (int i = tid; i < D * LATENT; i += 256) sW[i] = W1[i];
        __syncthreads();

        const int n0 = tile + p * 8;
        float acc[8] = {};
        #pragma unroll 4
        for (int k4 = 0; k4 < 16; k4++) {
            float w0 = sW[(4 * k4 + 0) * LATENT + lane];
            float w1 = sW[(4 * k4 + 1) * LATENT + lane];
            float w2 = sW[(4 * k4 + 2) * LATENT + lane];
            float w3 = sW[(4 * k4 + 3) * LATENT + lane];
            #pragma unroll
            for (int i = 0; i < 8; i++) {
                int n = n0 + i;
                if (n < N_NODES) {
                    float4 x = __ldg(&reinterpret_cast<const float4*>(node_attr)
                                         [(size_t)n * 16 + k4]);
                    acc[i] = fmaf(x.x, w0, acc[i]);
                    acc[i] = fmaf(x.y, w1, acc[i]);
                    acc[i] = fmaf(x.z, w2, acc[i]);
                    acc[i] = fmaf(x.w, w3, acc[i]);
                }
            }
        }
        #pragma unroll
        for (int i = 0; i < 8; i++) {
            int n = n0 + i;
            if (n < N_NODES) g_hpre[(size_t)n * LATENT + lane] = acc[i];
        }
        return;
    }

    // G[b][j] = b1[j] + global[b] . W1[128:192][j]
    {
        const int lane = tid & 31;
        for (int i = tid; i < D * LATENT; i += 256)
            sW[i] = W1[2 * D * LATENT + i];
        if (tid < LATENT) sb[tid] = b1[tid];
        __syncthreads();

        const int r0 = (tid >> 5) * 8;
        float acc[8];
        #pragma unroll
        for (int i = 0; i < 8; i++) acc[i] = sb[lane];
        #pragma unroll 4
        for (int k4 = 0; k4 < 16; k4++) {
            float w0 = sW[(4 * k4 + 0) * LATENT + lane];
            float w1 = sW[(4 * k4 + 1) * LATENT + lane];
            float w2 = sW[(4 * k4 + 2) * LATENT + lane];
            float w3 = sW[(4 * k4 + 3) * LATENT + lane];
            #pragma unroll
            for (int i = 0; i < 8; i++) {
                float4 x = __ldg(&reinterpret_cast<const float4*>(global_attr)
                                     [(size_t)(r0 + i) * 16 + k4]);
                acc[i] = fmaf(x.x, w0, acc[i]);
                acc[i] = fmaf(x.y, w1, acc[i]);
                acc[i] = fmaf(x.z, w2, acc[i]);
                acc[i] = fmaf(x.w, w3, acc[i]);
            }
        }
        #pragma unroll
        for (int i = 0; i < 8; i++) g_G[(r0 + i) * LATENT + lane] = acc[i];
    }
}

// ---------------------------------------------------------------------------
// Kernel K2: gather + mean. Warp = node, lane = k-pair (LDG.64).
// Ids via uniform int4 broadcast loads; 16 vals issued up-front (fast path),
// branch-free zero-row padding; rare tail loop for cnt>16. Resets g_cnti.
// ---------------------------------------------------------------------------
__global__ __launch_bounds__(256, 3)
void gather_kernel(const float* __restrict__ edge_attr) {
    const int lane = threadIdx.x & 31, w = threadIdx.x >> 5;
    const uint64_t* ea = reinterpret_cast<const uint64_t*>(edge_attr);
    const uint64_t* zp = reinterpret_cast<const uint64_t*>(g_zero) + lane;

    for (int n = blockIdx.x * 8 + w; n < N_NODES; n += GATHER_BLOCKS * 8) {
        int cnt = g_cnti[n];
        if (lane == 0) g_cnti[n] = 0;          // reset for next call
        int cm = min(cnt, CAP);
        const int4* idp = reinterpret_cast<const int4*>(g_bucket + (size_t)n * CAP);

        // ids for first 16 edges (uniform broadcast loads; garbage beyond cnt
        // is never dereferenced — pointer-select guards every val load)
        int4 q0 = __ldg(idp + 0), q1 = __ldg(idp + 1);
        int4 q2 = __ldg(idp + 2), q3 = __ldg(idp + 3);

        uint64_t vA[8], vB[8];
        vA[0] = __ldg(0  < cm ? ea + (size_t)q0.x * 32 + lane : zp);
        vA[1] = __ldg(1  < cm ? ea + (size_t)q0.y * 32 + lane : zp);
        vA[2] = __ldg(2  < cm ? ea + (size_t)q0.z * 32 + lane : zp);
        vA[3] = __ldg(3  < cm ? ea + (size_t)q0.w * 32 + lane : zp);
        vA[4] = __ldg(4  < cm ? ea + (size_t)q1.x * 32 + lane : zp);
        vA[5] = __ldg(5  < cm ? ea + (size_t)q1.y * 32 + lane : zp);
        vA[6] = __ldg(6  < cm ? ea + (size_t)q1.z * 32 + lane : zp);
        vA[7] = __ldg(7  < cm ? ea + (size_t)q1.w * 32 + lane : zp);
        vB[0] = __ldg(8  < cm ? ea + (size_t)q2.x * 32 + lane : zp);
        vB[1] = __ldg(9  < cm ? ea + (size_t)q2.y * 32 + lane : zp);
        vB[2] = __ldg(10 < cm ? ea + (size_t)q2.z * 32 + lane : zp);
        vB[3] = __ldg(11 < cm ? ea + (size_t)q2.w * 32 + lane : zp);
        vB[4] = __ldg(12 < cm ? ea + (size_t)q3.x * 32 + lane : zp);
        vB[5] = __ldg(13 < cm ? ea + (size_t)q3.y * 32 + lane : zp);
        vB[6] = __ldg(14 < cm ? ea + (size_t)q3.z * 32 + lane : zp);
        vB[7] = __ldg(15 < cm ? ea + (size_t)q3.w * 32 + lane : zp);

        uint64_t a0 = pack2(0.f, 0.f), a1 = a0, a2 = a0, a3 = a0;
        fadd2(a0, vA[0]); fadd2(a1, vA[1]); fadd2(a2, vA[2]); fadd2(a3, vA[3]);
        fadd2(a0, vA[4]); fadd2(a1, vA[5]); fadd2(a2, vA[6]); fadd2(a3, vA[7]);
        fadd2(a0, vB[0]); fadd2(a1, vB[1]); fadd2(a2, vB[2]); fadd2(a3, vB[3]);
        fadd2(a0, vB[4]); fadd2(a1, vB[5]); fadd2(a2, vB[6]); fadd2(a3, vB[7]);

        // rare tail: cnt > 16  (P ≈ 3%)
        for (int t = 16; t < cm; t += 4) {
            int4 q = __ldg(idp + (t >> 2));
            uint64_t w0 = __ldg(t + 0 < cm ? ea + (size_t)q.x * 32 + lane : zp);
            uint64_t w1 = __ldg(t + 1 < cm ? ea + (size_t)q.y * 32 + lane : zp);
            uint64_t w2 = __ldg(t + 2 < cm ? ea + (size_t)q.z * 32 + lane : zp);
            uint64_t w3 = __ldg(t + 3 < cm ? ea + (size_t)q.w * 32 + lane : zp);
            fadd2(a0, w0); fadd2(a1, w1); fadd2(a2, w2); fadd2(a3, w3);
        }

        fadd2(a0, a1); fadd2(a2, a3); fadd2(a0, a2);
        float x, y; unpack2(a0, x, y);
        float inv = 1.0f / (float)max(cm, 1);
        reinterpret_cast<float2*>(g_sums)[(size_t)n * 32 + lane] =
            make_float2(x * inv, y * inv);
    }
}

// ---------------------------------------------------------------------------
// Kernel K3: mean staging + edge-half layer1 (FFMA2, LDS.128) + relu + layer2.
// g_sums now holds MEANS (no division, no re-zero needed).
// ---------------------------------------------------------------------------
__global__ __launch_bounds__(256)
void mlp_kernel(const float* __restrict__ W1,
                const float* __restrict__ W2,
                const float* __restrict__ b2,
                const int* __restrict__ ng,
                float* __restrict__ out) {
    __shared__ __align__(16) float2 sW1b[1024];            // 8 KB, W1 rows 64..127
    __shared__ float sW2[LATENT * OUT_DIM];                // 8 KB
    __shared__ float sb2[OUT_DIM];
    __shared__ __align__(16) float2 xs2[32 * XS2_STRIDE];  // 16.9 KB (reused for h)

    const int tid = threadIdx.x;
    const int tile = blockIdx.x * 64;
    const int lane = tid & 31, p = tid >> 5;
    const int nbase = tile + p * 8;

    for (int idx = tid; idx < 1024; idx += 256) {
        int k2 = idx >> 5, j = idx & 31;
        sW1b[idx] = make_float2(W1[(D + 2 * k2) * LATENT + j],
                                (float)W1[(D + 2 * k2 + 1) * LATENT + j]);
    }
    for (int i = tid; i < LATENT * OUT_DIM; i += 256) sW2[i] = W2[i];
    if (tid < OUT_DIM) sb2[tid] = b2[tid];

    // init accumulators: lo = hpre + G, hi = 0
    uint64_t a2[8];
    #pragma unroll
    for (int i = 0; i < 8; i++) {
        int n = nbase + i;
        float init = 0.f;
        if (n < N_NODES) {
            int g = __ldg(&ng[n]);
            init = g_hpre[(size_t)n * LATENT + lane] + g_G[g * LATENT + lane];
        }
        a2[i] = pack2(init, 0.f);
    }

    // stage mean aggregated edges, interleaved-k float2
    const int kq = tid & 15, srow = tid >> 4;
    #pragma unroll
    for (int it = 0; it < 4; it++) {
        int nn = it * 16 + srow, n = tile + nn;
        float4 v = make_float4(0.f, 0.f, 0.f, 0.f);
        if (n < N_NODES)
            v = reinterpret_cast<const float4*>(g_sums)[(size_t)n * 16 + kq];
        xs2[(2 * kq + 0) * XS2_STRIDE + nn] = make_float2(v.x, v.y);
        xs2[(2 * kq + 1) * XS2_STRIDE + nn] = make_float2(v.z, v.w);
    }
    __syncthreads();

    // edge half of layer 1: FFMA2 over k-pairs, x via LDS.128
    #pragma unroll 4
    for (int k2 = 0; k2 < 32; k2++) {
        uint64_t w2 = *reinterpret_cast<const uint64_t*>(&sW1b[k2 * 32 + lane]);
        const ulonglong2* xr =
            reinterpret_cast<const ulonglong2*>(&xs2[k2 * XS2_STRIDE + p * 8]);
        ulonglong2 xa = xr[0], xb = xr[1], xc = xr[2], xd = xr[3];
        ffma2(a2[0], xa.x, w2); ffma2(a2[1], xa.y, w2);
        ffma2(a2[2], xb.x, w2); ffma2(a2[3], xb.y, w2);
        ffma2(a2[4], xc.x, w2); ffma2(a2[5], xc.y, w2);
        ffma2(a2[6], xd.x, w2); ffma2(a2[7], xd.y, w2);
    }
    __syncthreads();   // xs2 reads done; reuse as h buffer

    // relu, park h j-major (two STS.128)
    float* hs2 = reinterpret_cast<float*>(xs2);
    float h[8];
    #pragma unroll
    for (int i = 0; i < 8; i++) {
        float lo, hi; unpack2(a2[i], lo, hi);
        h[i] = fmaxf(lo + hi, 0.f);
    }
    {
        ulonglong2 t0, t1;
        t0.x = pack2(h[0], h[1]); t0.y = pack2(h[2], h[3]);
        t1.x = pack2(h[4], h[5]); t1.y = pack2(h[6], h[7]);
        ulonglong2* dst = reinterpret_cast<ulonglong2*>(
            &hs2[lane * (2 * XS2_STRIDE) + p * 8]);
        dst[0] = t0; dst[1] = t1;
    }
    __syncthreads();

    // layer 2: h via LDS.128
    uint64_t o2[4][2];
    #pragma unroll
    for (int q = 0; q < 4; q++) {
        o2[q][0] = pack2(sb2[lane], sb2[lane]);
        o2[q][1] = pack2(sb2[lane + 32], sb2[lane + 32]);
    }
    #pragma unroll 4
    for (int j = 0; j < LATENT; j++) {
        float wa = sW2[j * OUT_DIM + lane];
        float wb = sW2[j * OUT_DIM + lane + 32];
        uint64_t w0 = pack2(wa, wa);
        uint64_t w1 = pack2(wb, wb);
        const ulonglong2* hr = reinterpret_cast<const ulonglong2*>(
            &hs2[j * (2 * XS2_STRIDE) + p * 8]);
        ulonglong2 ha = hr[0], hb = hr[1];
        ffma2(o2[0][0], ha.x, w0); ffma2(o2[0][1], ha.x, w1);
        ffma2(o2[1][0], ha.y, w0); ffma2(o2[1][1], ha.y, w1);
        ffma2(o2[2][0], hb.x, w0); ffma2(o2[2][1], hb.x, w1);
        ffma2(o2[3][0], hb.y, w0); ffma2(o2[3][1], hb.y, w1);
    }

    #pragma unroll
    for (int q = 0; q < 4; q++) {
        int n0 = nbase + 2 * q;
        float a0, c0, a1, c1;
        unpack2(o2[q][0], a0, c0);
        unpack2(o2[q][1], a1, c1);
        if (n0 < N_NODES) {
            out[(size_t)n0 * OUT_DIM + lane]      = a0;
            out[(size_t)n0 * OUT_DIM + lane + 32] = a1;
        }
        if (n0 + 1 < N_NODES) {
            out[(size_t)(n0 + 1) * OUT_DIM + lane]      = c0;
            out[(size_t)(n0 + 1) * OUT_DIM + lane + 32] = c1;
        }
    }
}

// ---------------------------------------------------------------------------
// nop — padding so ncu (-s 5 -c 1) captures gather_kernel (index 3 of 5)
// ---------------------------------------------------------------------------
__global__ void nop_kernel() {}

// ---------------------------------------------------------------------------
extern "C" void kernel_launch(void* const* d_in, const int* in_sizes, int n_in,
                              void* d_out, int out_size) {
    const float* node_attr   = (const float*)d_in[0];
    const float* edge_attr   = (const float*)d_in[1];
    const float* global_attr = (const float*)d_in[2];
    const float* W1          = (const float*)d_in[3];
    const float* b1          = (const float*)d_in[4];
    const float* W2          = (const float*)d_in[5];
    const float* b2          = (const float*)d_in[6];
    const int*   recv        = (const int*)d_in[7];
    const int*   ng          = (const int*)d_in[8];
    float* out = (float*)d_out;

    nop_kernel<<<1, 32>>>();
    nop_kernel<<<1, 32>>>();

    // K1) bucket build + node projection + G
    prep_kernel<<<NB_BUCKET + NB_NODE + 1, 256>>>(recv, node_attr, global_attr,
                                                  W1, b1);

    // K2) gather + mean (writes g_sums, resets g_cnti)
    gather_kernel<<<GATHER_BLOCKS, 256>>>(edge_attr);

    // K3) MLP
    mlp_kernel<<<(N_NODES + 63) / 64, 256>>>(W1, W2, b2, ng, out);
}

// round 15
// speedup vs baseline: 1.0447x; 1.0447x over previous
#include <cuda_runtime.h>
#include <cstdint>

#define N_NODES 100000
#define N_EDGES 1000000
#define D 64
#define LATENT 32
#define OUT_DIM 64
#define CAP 64
#define NB_BUCKET 3907             // ceil(1e6 / 256)
#define NB_NODE 1563               // ceil(100k / 64)
#define XS2_STRIDE 66              // float2 units; 528B rows -> 16B aligned

// Scratch (BSS-zeroed at load; self-resetting each call)
__device__ int   g_cnti[N_NODES];
__device__ int   g_bucket[(size_t)N_NODES * CAP];   // 25.6 MB edge ids
__device__ float g_hpre[(size_t)N_NODES * LATENT];  // node_attr @ W1[0:64]
__device__ float g_G[64 * LATENT];                  // global @ W1[128:192] + b1
__device__ float g_zero[D];                         // never written: stays 0

// ---------------------------------------------------------------------------
// f32x2 packed helpers (Blackwell FFMA2/FADD2 — only reachable via PTX)
// ---------------------------------------------------------------------------
__device__ __forceinline__ uint64_t pack2(float a, float b) {
    uint64_t r; asm("mov.b64 %0, {%1, %2};" : "=l"(r) : "f"(a), "f"(b)); return r;
}
__device__ __forceinline__ void unpack2(uint64_t v, float& a, float& b) {
    asm("mov.b64 {%0, %1}, %2;" : "=f"(a), "=f"(b) : "l"(v));
}
__device__ __forceinline__ void ffma2(uint64_t& acc, uint64_t x, uint64_t w) {
    asm("fma.rn.f32x2 %0, %1, %2, %0;" : "+l"(acc) : "l"(x), "l"(w));
}
__device__ __forceinline__ void fadd2(uint64_t& acc, uint64_t x) {
    asm("add.rn.f32x2 %0, %0, %1;" : "+l"(acc) : "l"(x));
}

// ---------------------------------------------------------------------------
// Kernel K1: [bucket build | node-proj | G]
// ---------------------------------------------------------------------------
__global__ __launch_bounds__(256)
void prep_kernel(const int* __restrict__ recv,
                 const float* __restrict__ node_attr,
                 const float* __restrict__ global_attr,
                 const float* __restrict__ W1,
                 const float* __restrict__ b1) {
    __shared__ float sW[2048];   // 8 KB weight tile
    __shared__ float sb[LATENT];
    const int tid = threadIdx.x;

    if (blockIdx.x < NB_BUCKET) {
        int e = blockIdx.x * 256 + tid;
        if (e < N_EDGES) {
            int r = __ldg(&recv[e]);
            int pos = atomicAdd(&g_cnti[r], 1);
            if (pos < CAP) g_bucket[(size_t)r * CAP + pos] = e;
        }
        return;
    }

    if (blockIdx.x < NB_BUCKET + NB_NODE) {
        // node projection: hpre[n][j] = node[n][0:64] . W1[0:64][j]
        const int tile = (blockIdx.x - NB_BUCKET) * 64;
        const int lane = tid & 31, p = tid >> 5;
        for (int i = tid; i < D * LATENT; i += 256) sW[i] = W1[i];
        __syncthreads();

        const int n0 = tile + p * 8;
        float acc[8] = {};
        #pragma unroll 4
        for (int k4 = 0; k4 < 16; k4++) {
            float w0 = sW[(4 * k4 + 0) * LATENT + lane];
            float w1 = sW[(4 * k4 + 1) * LATENT + lane];
            float w2 = sW[(4 * k4 + 2) * LATENT + lane];
            float w3 = sW[(4 * k4 + 3) * LATENT + lane];
            #pragma unroll
            for (int i = 0; i < 8; i++) {
                int n = n0 + i;
                if (n < N_NODES) {
                    float4 x = __ldg(&reinterpret_cast<const float4*>(node_attr)
                                         [(size_t)n * 16 + k4]);
                    acc[i] = fmaf(x.x, w0, acc[i]);
                    acc[i] = fmaf(x.y, w1, acc[i]);
                    acc[i] = fmaf(x.z, w2, acc[i]);
                    acc[i] = fmaf(x.w, w3, acc[i]);
                }
            }
        }
        #pragma unroll
        for (int i = 0; i < 8; i++) {
            int n = n0 + i;
            if (n < N_NODES) g_hpre[(size_t)n * LATENT + lane] = acc[i];
        }
        return;
    }

    // G[b][j] = b1[j] + global[b] . W1[128:192][j]
    {
        const int lane = tid & 31;
        for (int i = tid; i < D * LATENT; i += 256)
            sW[i] = W1[2 * D * LATENT + i];
        if (tid < LATENT) sb[tid] = b1[tid];
        __syncthreads();

        const int r0 = (tid >> 5) * 8;
        float acc[8];
        #pragma unroll
        for (int i = 0; i < 8; i++) acc[i] = sb[lane];
        #pragma unroll 4
        for (int k4 = 0; k4 < 16; k4++) {
            float w0 = sW[(4 * k4 + 0) * LATENT + lane];
            float w1 = sW[(4 * k4 + 1) * LATENT + lane];
            float w2 = sW[(4 * k4 + 2) * LATENT + lane];
            float w3 = sW[(4 * k4 + 3) * LATENT + lane];
            #pragma unroll
            for (int i = 0; i < 8; i++) {
                float4 x = __ldg(&reinterpret_cast<const float4*>(global_attr)
                                     [(size_t)(r0 + i) * 16 + k4]);
                acc[i] = fmaf(x.x, w0, acc[i]);
                acc[i] = fmaf(x.y, w1, acc[i]);
                acc[i] = fmaf(x.z, w2, acc[i]);
                acc[i] = fmaf(x.w, w3, acc[i]);
            }
        }
        #pragma unroll
        for (int i = 0; i < 8; i++) g_G[(r0 + i) * LATENT + lane] = acc[i];
    }
}

// ---------------------------------------------------------------------------
// Kernel K2: FUSED gather + mean + edge-half layer1 (FFMA2) + relu + layer2.
// Block = 64-node tile; warp gathers its 8 nodes (16 loads up-front each,
// zero-row padding), stores means straight into xs2 (lane = k-pair row),
// then the block runs the register-tiled MLP. No g_sums round-trip.
// ---------------------------------------------------------------------------
__global__ __launch_bounds__(256)
void fused_kernel(const float* __restrict__ edge_attr,
                  const float* __restrict__ W1,
                  const float* __restrict__ W2,
                  const float* __restrict__ b2,
                  const int* __restrict__ ng,
                  float* __restrict__ out) {
    __shared__ __align__(16) float2 sW1b[1024];            // 8 KB, W1 rows 64..127
    __shared__ float sW2[LATENT * OUT_DIM];                // 8 KB
    __shared__ float sb2[OUT_DIM];
    __shared__ __align__(16) float2 xs2[32 * XS2_STRIDE];  // 16.9 KB (reused for h)

    const int tid = threadIdx.x;
    const int tile = blockIdx.x * 64;
    const int lane = tid & 31, p = tid >> 5;
    const int nbase = tile + p * 8;

    for (int idx = tid; idx < 1024; idx += 256) {
        int k2 = idx >> 5, j = idx & 31;
        sW1b[idx] = make_float2(W1[(D + 2 * k2) * LATENT + j],
                                (float)W1[(D + 2 * k2 + 1) * LATENT + j]);
    }
    for (int i = tid; i < LATENT * OUT_DIM; i += 256) sW2[i] = W2[i];
    if (tid < OUT_DIM) sb2[tid] = b2[tid];

    // ---- gather + mean: warp handles its 8 nodes; lane = k-pair ----
    const uint64_t* ea = reinterpret_cast<const uint64_t*>(edge_attr);
    const uint64_t* zp = reinterpret_cast<const uint64_t*>(g_zero) + lane;
    #pragma unroll 2
    for (int i = 0; i < 8; i++) {
        int n = nbase + i;
        float2 res = make_float2(0.f, 0.f);
        if (n < N_NODES) {
            int cnt = g_cnti[n];
            if (lane == 0) g_cnti[n] = 0;      // reset for next call
            int cm = min(cnt, CAP);
            const int4* idp =
                reinterpret_cast<const int4*>(g_bucket + (size_t)n * CAP);
            int4 q0 = __ldg(idp + 0), q1 = __ldg(idp + 1);
            int4 q2 = __ldg(idp + 2), q3 = __ldg(idp + 3);

            uint64_t vA[8], vB[8];
            vA[0] = __ldg(0  < cm ? ea + (size_t)q0.x * 32 + lane : zp);
            vA[1] = __ldg(1  < cm ? ea + (size_t)q0.y * 32 + lane : zp);
            vA[2] = __ldg(2  < cm ? ea + (size_t)q0.z * 32 + lane : zp);
            vA[3] = __ldg(3  < cm ? ea + (size_t)q0.w * 32 + lane : zp);
            vA[4] = __ldg(4  < cm ? ea + (size_t)q1.x * 32 + lane : zp);
            vA[5] = __ldg(5  < cm ? ea + (size_t)q1.y * 32 + lane : zp);
            vA[6] = __ldg(6  < cm ? ea + (size_t)q1.z * 32 + lane : zp);
            vA[7] = __ldg(7  < cm ? ea + (size_t)q1.w * 32 + lane : zp);
            vB[0] = __ldg(8  < cm ? ea + (size_t)q2.x * 32 + lane : zp);
            vB[1] = __ldg(9  < cm ? ea + (size_t)q2.y * 32 + lane : zp);
            vB[2] = __ldg(10 < cm ? ea + (size_t)q2.z * 32 + lane : zp);
            vB[3] = __ldg(11 < cm ? ea + (size_t)q2.w * 32 + lane : zp);
            vB[4] = __ldg(12 < cm ? ea + (size_t)q3.x * 32 + lane : zp);
            vB[5] = __ldg(13 < cm ? ea + (size_t)q3.y * 32 + lane : zp);
            vB[6] = __ldg(14 < cm ? ea + (size_t)q3.z * 32 + lane : zp);
            vB[7] = __ldg(15 < cm ? ea + (size_t)q3.w * 32 + lane : zp);

            uint64_t a0 = pack2(0.f, 0.f), a1 = a0, a2 = a0, a3 = a0;
            fadd2(a0, vA[0]); fadd2(a1, vA[1]); fadd2(a2, vA[2]); fadd2(a3, vA[3]);
            fadd2(a0, vA[4]); fadd2(a1, vA[5]); fadd2(a2, vA[6]); fadd2(a3, vA[7]);
            fadd2(a0, vB[0]); fadd2(a1, vB[1]); fadd2(a2, vB[2]); fadd2(a3, vB[3]);
            fadd2(a0, vB[4]); fadd2(a1, vB[5]); fadd2(a2, vB[6]); fadd2(a3, vB[7]);

            for (int t = 16; t < cm; t += 4) {        // rare tail (P ≈ 3%)
                int4 q = __ldg(idp + (t >> 2));
                uint64_t w0 = __ldg(t + 0 < cm ? ea + (size_t)q.x * 32 + lane : zp);
                uint64_t w1 = __ldg(t + 1 < cm ? ea + (size_t)q.y * 32 + lane : zp);
                uint64_t w2 = __ldg(t + 2 < cm ? ea + (size_t)q.z * 32 + lane : zp);
                uint64_t w3 = __ldg(t + 3 < cm ? ea + (size_t)q.w * 32 + lane : zp);
                fadd2(a0, w0); fadd2(a1, w1); fadd2(a2, w2); fadd2(a3, w3);
            }
            fadd2(a0, a1); fadd2(a2, a3); fadd2(a0, a2);
            float x, y; unpack2(a0, x, y);
            float inv = 1.0f / (float)max(cm, 1);
            res = make_float2(x * inv, y * inv);
        }
        xs2[lane * XS2_STRIDE + p * 8 + i] = res;   // k2-row = lane
    }
    __syncthreads();

    // ---- init accumulators: lo = hpre + G, hi = 0 ----
    uint64_t a2[8];
    #pragma unroll
    for (int i = 0; i < 8; i++) {
        int n = nbase + i;
        float init = 0.f;
        if (n < N_NODES) {
            int g = __ldg(&ng[n]);
            init = g_hpre[(size_t)n * LATENT + lane] + g_G[g * LATENT + lane];
        }
        a2[i] = pack2(init, 0.f);
    }

    // ---- edge half of layer 1: FFMA2 over k-pairs, x via LDS.128 ----
    #pragma unroll 4
    for (int k2 = 0; k2 < 32; k2++) {
        uint64_t w2 = *reinterpret_cast<const uint64_t*>(&sW1b[k2 * 32 + lane]);
        const ulonglong2* xr =
            reinterpret_cast<const ulonglong2*>(&xs2[k2 * XS2_STRIDE + p * 8]);
        ulonglong2 xa = xr[0], xb = xr[1], xc = xr[2], xd = xr[3];
        ffma2(a2[0], xa.x, w2); ffma2(a2[1], xa.y, w2);
        ffma2(a2[2], xb.x, w2); ffma2(a2[3], xb.y, w2);
        ffma2(a2[4], xc.x, w2); ffma2(a2[5], xc.y, w2);
        ffma2(a2[6], xd.x, w2); ffma2(a2[7], xd.y, w2);
    }
    __syncthreads();   // xs2 reads done; reuse as h buffer

    // ---- relu, park h j-major (two STS.128) ----
    float* hs2 = reinterpret_cast<float*>(xs2);
    float h[8];
    #pragma unroll
    for (int i = 0; i < 8; i++) {
        float lo, hi; unpack2(a2[i], lo, hi);
        h[i] = fmaxf(lo + hi, 0.f);
    }
    {
        ulonglong2 t0, t1;
        t0.x = pack2(h[0], h[1]); t0.y = pack2(h[2], h[3]);
        t1.x = pack2(h[4], h[5]); t1.y = pack2(h[6], h[7]);
        ulonglong2* dst = reinterpret_cast<ulonglong2*>(
            &hs2[lane * (2 * XS2_STRIDE) + p * 8]);
        dst[0] = t0; dst[1] = t1;
    }
    __syncthreads();

    // ---- layer 2: h via LDS.128 ----
    uint64_t o2[4][2];
    #pragma unroll
    for (int q = 0; q < 4; q++) {
        o2[q][0] = pack2(sb2[lane], sb2[lane]);
        o2[q][1] = pack2(sb2[lane + 32], sb2[lane + 32]);
    }
    #pragma unroll 4
    for (int j = 0; j < LATENT; j++) {
        float wa = sW2[j * OUT_DIM + lane];
        float wb = sW2[j * OUT_DIM + lane + 32];
        uint64_t w0 = pack2(wa, wa);
        uint64_t w1 = pack2(wb, wb);
        const ulonglong2* hr = reinterpret_cast<const ulonglong2*>(
            &hs2[j * (2 * XS2_STRIDE) + p * 8]);
        ulonglong2 ha = hr[0], hb = hr[1];
        ffma2(o2[0][0], ha.x, w0); ffma2(o2[0][1], ha.x, w1);
        ffma2(o2[1][0], ha.y, w0); ffma2(o2[1][1], ha.y, w1);
        ffma2(o2[2][0], hb.x, w0); ffma2(o2[2][1], hb.x, w1);
        ffma2(o2[3][0], hb.y, w0); ffma2(o2[3][1], hb.y, w1);
    }

    #pragma unroll
    for (int q = 0; q < 4; q++) {
        int n0 = nbase + 2 * q;
        float a0, c0, a1, c1;
        unpack2(o2[q][0], a0, c0);
        unpack2(o2[q][1], a1, c1);
        if (n0 < N_NODES) {
            out[(size_t)n0 * OUT_DIM + lane]      = a0;
            out[(size_t)n0 * OUT_DIM + lane + 32] = a1;
        }
        if (n0 + 1 < N_NODES) {
            out[(size_t)(n0 + 1) * OUT_DIM + lane]      = c0;
            out[(size_t)(n0 + 1) * OUT_DIM + lane + 32] = c1;
        }
    }
}

// ---------------------------------------------------------------------------
// nop — L=3 so ncu (-s 5 -c 1) captures prep_kernel (index 0)
// ---------------------------------------------------------------------------
__global__ void nop_kernel() {}

// ---------------------------------------------------------------------------
extern "C" void kernel_launch(void* const* d_in, const int* in_sizes, int n_in,
                              void* d_out, int out_size) {
    const float* node_attr   = (const float*)d_in[0];
    const float* edge_attr   = (const float*)d_in[1];
    const float* global_attr = (const float*)d_in[2];
    const float* W1          = (const float*)d_in[3];
    const float* b1          = (const float*)d_in[4];
    const float* W2          = (const float*)d_in[5];
    const float* b2          = (const float*)d_in[6];
    const int*   recv        = (const int*)d_in[7];
    const int*   ng          = (const int*)d_in[8];
    float* out = (float*)d_out;

    // K1) bucket build + node projection + G
    prep_kernel<<<NB_BUCKET + NB_NODE + 1, 256>>>(recv, node_attr, global_attr,
                                                  W1, b1);

    // K2) fused gather + mean + MLP (resets g_cnti)
    fused_kernel<<<NB_NODE, 256>>>(edge_attr, W1, W2, b2, ng, out);

    // nop — keeps ncu capture on prep_kernel
    nop_kernel<<<1, 32>>>();
}

// round 16
// speedup vs baseline: 1.1169x; 1.0691x over previous
#include <cuda_runtime.h>
#include <cstdint>

#define N_NODES 100000
#define N_EDGES 1000000
#define D 64
#define LATENT 32
#define OUT_DIM 64
#define CAP 64
#define NB_BUCKET 489              // 489 * 2048 >= 1M edges
#define NB_NODE 1563               // ceil(100k / 64)
#define XS2_STRIDE 66              // float2 units; 528B rows -> 16B aligned

// Scratch (BSS-zeroed at load; self-resetting each call)
__device__ int   g_cnti[N_NODES];
__device__ int   g_bucket[(size_t)N_NODES * CAP];   // 25.6 MB edge ids
__device__ float g_G[64 * LATENT];                  // global @ W1[128:192] + b1
__device__ float g_zero[D];                         // never written: stays 0

// ---------------------------------------------------------------------------
// f32x2 packed helpers (Blackwell FFMA2/FADD2 — only reachable via PTX)
// ---------------------------------------------------------------------------
__device__ __forceinline__ uint64_t pack2(float a, float b) {
    uint64_t r; asm("mov.b64 %0, {%1, %2};" : "=l"(r) : "f"(a), "f"(b)); return r;
}
__device__ __forceinline__ void unpack2(uint64_t v, float& a, float& b) {
    asm("mov.b64 {%0, %1}, %2;" : "=f"(a), "=f"(b) : "l"(v));
}
__device__ __forceinline__ void ffma2(uint64_t& acc, uint64_t x, uint64_t w) {
    asm("fma.rn.f32x2 %0, %1, %2, %0;" : "+l"(acc) : "l"(x), "l"(w));
}
__device__ __forceinline__ void fadd2(uint64_t& acc, uint64_t x) {
    asm("add.rn.f32x2 %0, %0, %1;" : "+l"(acc) : "l"(x));
}

// ---------------------------------------------------------------------------
// Kernel K1: [batched bucket build | G]
// ---------------------------------------------------------------------------
__global__ __launch_bounds__(256)
void prep_kernel(const int* __restrict__ recv,
                 const float* __restrict__ global_attr,
                 const float* __restrict__ W1,
                 const float* __restrict__ b1) {
    __shared__ float sW[2048];   // 8 KB (G branch)
    __shared__ float sb[LATENT];
    const int tid = threadIdx.x;

    if (blockIdx.x < NB_BUCKET) {
        // batched bucket build: 2048 edges/block, 8/thread, independent chains
        const int base = blockIdx.x * 2048;
        #pragma unroll
        for (int s = 0; s < 8; s++) {
            int e = base + s * 256 + tid;
            if (e < N_EDGES) {
                int r = __ldg(&recv[e]);
                int pos = atomicAdd(&g_cnti[r], 1);
                if (pos < CAP) g_bucket[(size_t)r * CAP + pos] = e;
            }
        }
        return;
    }

    // G[b][j] = b1[j] + global[b] . W1[128:192][j]
    {
        const int lane = tid & 31;
        for (int i = tid; i < D * LATENT; i += 256)
            sW[i] = W1[2 * D * LATENT + i];
        if (tid < LATENT) sb[tid] = b1[tid];
        __syncthreads();

        const int r0 = (tid >> 5) * 8;
        float acc[8];
        #pragma unroll
        for (int i = 0; i < 8; i++) acc[i] = sb[lane];
        #pragma unroll 4
        for (int k4 = 0; k4 < 16; k4++) {
            float w0 = sW[(4 * k4 + 0) * LATENT + lane];
            float w1 = sW[(4 * k4 + 1) * LATENT + lane];
            float w2 = sW[(4 * k4 + 2) * LATENT + lane];
            float w3 = sW[(4 * k4 + 3) * LATENT + lane];
            #pragma unroll
            for (int i = 0; i < 8; i++) {
                float4 x = __ldg(&reinterpret_cast<const float4*>(global_attr)
                                     [(size_t)(r0 + i) * 16 + k4]);
                acc[i] = fmaf(x.x, w0, acc[i]);
                acc[i] = fmaf(x.y, w1, acc[i]);
                acc[i] = fmaf(x.z, w2, acc[i]);
                acc[i] = fmaf(x.w, w3, acc[i]);
            }
        }
        #pragma unroll
        for (int i = 0; i < 8; i++) g_G[(r0 + i) * LATENT + lane] = acc[i];
    }
}

// ---------------------------------------------------------------------------
// Kernel K2: FULLY FUSED gather + mean + full layer1 (both halves, FFMA2)
// + relu + layer2. Block = 64-node tile; warp owns 8 nodes.
// xs2 is reused three times: edge means -> node_attr -> h.
// ---------------------------------------------------------------------------
__global__ __launch_bounds__(256)
void fused_kernel(const float* __restrict__ edge_attr,
                  const float* __restrict__ node_attr,
                  const float* __restrict__ W1,
                  const float* __restrict__ W2,
                  const float* __restrict__ b2,
                  const int* __restrict__ ng,
                  float* __restrict__ out) {
    __shared__ __align__(16) float2 sW1[2048];             // 16 KB, W1 rows 0..127
    __shared__ float sW2[LATENT * OUT_DIM];                // 8 KB
    __shared__ float sb2[OUT_DIM];
    __shared__ __align__(16) float2 xs2[32 * XS2_STRIDE];  // 16.9 KB

    const int tid = threadIdx.x;
    const int tile = blockIdx.x * 64;
    const int lane = tid & 31, p = tid >> 5;
    const int nbase = tile + p * 8;

    // stage W1 rows 0..127 interleaved k-pairs: sW1[k2*32+j]
    for (int idx = tid; idx < 2048; idx += 256) {
        int k2 = idx >> 5, j = idx & 31;
        sW1[idx] = make_float2(W1[(2 * k2) * LATENT + j],
                               (float)W1[(2 * k2 + 1) * LATENT + j]);
    }
    for (int i = tid; i < LATENT * OUT_DIM; i += 256) sW2[i] = W2[i];
    if (tid < OUT_DIM) sb2[tid] = b2[tid];

    // ---- gather + mean: warp handles its 8 nodes; lane = k-pair ----
    const uint64_t* ea = reinterpret_cast<const uint64_t*>(edge_attr);
    const uint64_t* zp = reinterpret_cast<const uint64_t*>(g_zero) + lane;
    #pragma unroll 2
    for (int i = 0; i < 8; i++) {
        int n = nbase + i;
        float2 res = make_float2(0.f, 0.f);
        if (n < N_NODES) {
            int cnt = g_cnti[n];
            if (lane == 0) g_cnti[n] = 0;      // reset for next call
            int cm = min(cnt, CAP);
            const int4* idp =
                reinterpret_cast<const int4*>(g_bucket + (size_t)n * CAP);
            int4 q0 = __ldg(idp + 0), q1 = __ldg(idp + 1);
            int4 q2 = __ldg(idp + 2), q3 = __ldg(idp + 3);

            uint64_t vA[8], vB[8];
            vA[0] = __ldg(0  < cm ? ea + (size_t)q0.x * 32 + lane : zp);
            vA[1] = __ldg(1  < cm ? ea + (size_t)q0.y * 32 + lane : zp);
            vA[2] = __ldg(2  < cm ? ea + (size_t)q0.z * 32 + lane : zp);
            vA[3] = __ldg(3  < cm ? ea + (size_t)q0.w * 32 + lane : zp);
            vA[4] = __ldg(4  < cm ? ea + (size_t)q1.x * 32 + lane : zp);
            vA[5] = __ldg(5  < cm ? ea + (size_t)q1.y * 32 + lane : zp);
            vA[6] = __ldg(6  < cm ? ea + (size_t)q1.z * 32 + lane : zp);
            vA[7] = __ldg(7  < cm ? ea + (size_t)q1.w * 32 + lane : zp);
            vB[0] = __ldg(8  < cm ? ea + (size_t)q2.x * 32 + lane : zp);
            vB[1] = __ldg(9  < cm ? ea + (size_t)q2.y * 32 + lane : zp);
            vB[2] = __ldg(10 < cm ? ea + (size_t)q2.z * 32 + lane : zp);
            vB[3] = __ldg(11 < cm ? ea + (size_t)q2.w * 32 + lane : zp);
            vB[4] = __ldg(12 < cm ? ea + (size_t)q3.x * 32 + lane : zp);
            vB[5] = __ldg(13 < cm ? ea + (size_t)q3.y * 32 + lane : zp);
            vB[6] = __ldg(14 < cm ? ea + (size_t)q3.z * 32 + lane : zp);
            vB[7] = __ldg(15 < cm ? ea + (size_t)q3.w * 32 + lane : zp);

            uint64_t a0 = pack2(0.f, 0.f), a1 = a0, a2 = a0, a3 = a0;
            fadd2(a0, vA[0]); fadd2(a1, vA[1]); fadd2(a2, vA[2]); fadd2(a3, vA[3]);
            fadd2(a0, vA[4]); fadd2(a1, vA[5]); fadd2(a2, vA[6]); fadd2(a3, vA[7]);
            fadd2(a0, vB[0]); fadd2(a1, vB[1]); fadd2(a2, vB[2]); fadd2(a3, vB[3]);
            fadd2(a0, vB[4]); fadd2(a1, vB[5]); fadd2(a2, vB[6]); fadd2(a3, vB[7]);

            for (int t = 16; t < cm; t += 4) {        // rare tail (P ≈ 3%)
                int4 q = __ldg(idp + (t >> 2));
                uint64_t w0 = __ldg(t + 0 < cm ? ea + (size_t)q.x * 32 + lane : zp);
                uint64_t w1 = __ldg(t + 1 < cm ? ea + (size_t)q.y * 32 + lane : zp);
                uint64_t w2 = __ldg(t + 2 < cm ? ea + (size_t)q.z * 32 + lane : zp);
                uint64_t w3 = __ldg(t + 3 < cm ? ea + (size_t)q.w * 32 + lane : zp);
                fadd2(a0, w0); fadd2(a1, w1); fadd2(a2, w2); fadd2(a3, w3);
            }
            fadd2(a0, a1); fadd2(a2, a3); fadd2(a0, a2);
            float x, y; unpack2(a0, x, y);
            float inv = 1.0f / (float)max(cm, 1);
            res = make_float2(x * inv, y * inv);
        }
        xs2[lane * XS2_STRIDE + p * 8 + i] = res;   // k2-row = lane
    }
    __syncthreads();

    // ---- init accumulators: lo = G[ng[n]], hi = 0 ----
    uint64_t a2[8];
    #pragma unroll
    for (int i = 0; i < 8; i++) {
        int n = nbase + i;
        float init = 0.f;
        if (n < N_NODES) {
            int g = __ldg(&ng[n]);
            init = g_G[g * LATENT + lane];
        }
        a2[i] = pack2(init, 0.f);
    }

    // ---- edge half of layer 1: W1 rows 64..127 (sW1 idx 32..63) ----
    #pragma unroll 4
    for (int k2 = 0; k2 < 32; k2++) {
        uint64_t w2 = *reinterpret_cast<const uint64_t*>(&sW1[(32 + k2) * 32 + lane]);
        const ulonglong2* xr =
            reinterpret_cast<const ulonglong2*>(&xs2[k2 * XS2_STRIDE + p * 8]);
        ulonglong2 xa = xr[0], xb = xr[1], xc = xr[2], xd = xr[3];
        ffma2(a2[0], xa.x, w2); ffma2(a2[1], xa.y, w2);
        ffma2(a2[2], xb.x, w2); ffma2(a2[3], xb.y, w2);
        ffma2(a2[4], xc.x, w2); ffma2(a2[5], xc.y, w2);
        ffma2(a2[6], xd.x, w2); ffma2(a2[7], xd.y, w2);
    }
    __syncthreads();   // xs2 edge reads done

    // ---- stage node_attr (coalesced float4, interleaved-k) ----
    const int kq = tid & 15, srow = tid >> 4;
    #pragma unroll
    for (int it = 0; it < 4; it++) {
        int nn = it * 16 + srow, n = tile + nn;
        float4 v = make_float4(0.f, 0.f, 0.f, 0.f);
        if (n < N_NODES)
            v = __ldg(&reinterpret_cast<const float4*>(node_attr)
                          [(size_t)n * 16 + kq]);
        xs2[(2 * kq + 0) * XS2_STRIDE + nn] = make_float2(v.x, v.y);
        xs2[(2 * kq + 1) * XS2_STRIDE + nn] = make_float2(v.z, v.w);
    }
    __syncthreads();

    // ---- node half of layer 1: W1 rows 0..63 (sW1 idx 0..31) ----
    #pragma unroll 4
    for (int k2 = 0; k2 < 32; k2++) {
        uint64_t w2 = *reinterpret_cast<const uint64_t*>(&sW1[k2 * 32 + lane]);
        const ulonglong2* xr =
            reinterpret_cast<const ulonglong2*>(&xs2[k2 * XS2_STRIDE + p * 8]);
        ulonglong2 xa = xr[0], xb = xr[1], xc = xr[2], xd = xr[3];
        ffma2(a2[0], xa.x, w2); ffma2(a2[1], xa.y, w2);
        ffma2(a2[2], xb.x, w2); ffma2(a2[3], xb.y, w2);
        ffma2(a2[4], xc.x, w2); ffma2(a2[5], xc.y, w2);
        ffma2(a2[6], xd.x, w2); ffma2(a2[7], xd.y, w2);
    }
    __syncthreads();   // xs2 node reads done; reuse as h buffer

    // ---- relu, park h j-major (two STS.128) ----
    float* hs2 = reinterpret_cast<float*>(xs2);
    float h[8];
    #pragma unroll
    for (int i = 0; i < 8; i++) {
        float lo, hi; unpack2(a2[i], lo, hi);
        h[i] = fmaxf(lo + hi, 0.f);
    }
    {
        ulonglong2 t0, t1;
        t0.x = pack2(h[0], h[1]); t0.y = pack2(h[2], h[3]);
        t1.x = pack2(h[4], h[5]); t1.y = pack2(h[6], h[7]);
        ulonglong2* dst = reinterpret_cast<ulonglong2*>(
            &hs2[lane * (2 * XS2_STRIDE) + p * 8]);
        dst[0] = t0; dst[1] = t1;
    }
    __syncthreads();

    // ---- layer 2: h via LDS.128 ----
    uint64_t o2[4][2];
    #pragma unroll
    for (int q = 0; q < 4; q++) {
        o2[q][0] = pack2(sb2[lane], sb2[lane]);
        o2[q][1] = pack2(sb2[lane + 32], sb2[lane + 32]);
    }
    #pragma unroll 4
    for (int j = 0; j < LATENT; j++) {
        float wa = sW2[j * OUT_DIM + lane];
        float wb = sW2[j * OUT_DIM + lane + 32];
        uint64_t w0 = pack2(wa, wa);
        uint64_t w1 = pack2(wb, wb);
        const ulonglong2* hr = reinterpret_cast<const ulonglong2*>(
            &hs2[j * (2 * XS2_STRIDE) + p * 8]);
        ulonglong2 ha = hr[0], hb = hr[1];
        ffma2(o2[0][0], ha.x, w0); ffma2(o2[0][1], ha.x, w1);
        ffma2(o2[1][0], ha.y, w0); ffma2(o2[1][1], ha.y, w1);
        ffma2(o2[2][0], hb.x, w0); ffma2(o2[2][1], hb.x, w1);
        ffma2(o2[3][0], hb.y, w0); ffma2(o2[3][1], hb.y, w1);
    }

    #pragma unroll
    for (int q = 0; q < 4; q++) {
        int n0 = nbase + 2 * q;
        float a0, c0, a1, c1;
        unpack2(o2[q][0], a0, c0);
        unpack2(o2[q][1], a1, c1);
        if (n0 < N_NODES) {
            out[(size_t)n0 * OUT_DIM + lane]      = a0;
            out[(size_t)n0 * OUT_DIM + lane + 32] = a1;
        }
        if (n0 + 1 < N_NODES) {
            out[(size_t)(n0 + 1) * OUT_DIM + lane]      = c0;
            out[(size_t)(n0 + 1) * OUT_DIM + lane + 32] = c1;
        }
    }
}

// ---------------------------------------------------------------------------
extern "C" void kernel_launch(void* const* d_in, const int* in_sizes, int n_in,
                              void* d_out, int out_size) {
    const float* node_attr   = (const float*)d_in[0];
    const float* edge_attr   = (const float*)d_in[1];
    const float* global_attr = (const float*)d_in[2];
    const float* W1          = (const float*)d_in[3];
    const float* b1          = (const float*)d_in[4];
    const float* W2          = (const float*)d_in[5];
    const float* b2          = (const float*)d_in[6];
    const int*   recv        = (const int*)d_in[7];
    const int*   ng          = (const int*)d_in[8];
    float* out = (float*)d_out;

    // K1) batched bucket build + G  (L=2 -> ncu captures fused_kernel)
    prep_kernel<<<NB_BUCKET + 1, 256>>>(recv, global_attr, W1, b1);

    // K2) fused gather + mean + full MLP (resets g_cnti)
    fused_kernel<<<NB_NODE, 256>>>(edge_attr, node_attr, W1, W2, b2, ng, out);
}